// round 16
// baseline (speedup 1.0000x reference)
#include <cuda_runtime.h>

#define C 256
#define H 8
#define NUM_DST 256
#define NMAX 50000
#define EMAX 300000
#define LISTCAP 8192
#define BCAP 4096         // smem-resident BFS edge cap (expected ~1536)
#define HB 256            // histogram/scatter blocks
#define INV_SQRT_DH 0.17677669529663687f
#define LOG2E 1.4426950408889634f
#define USCALE (INV_SQRT_DH * LOG2E)
#define LN_EPS 1e-5f
#define SPLIT 8           // blocks per dst bucket
#define AGGSZ (NUM_DST * H * C)   // 524288

typedef unsigned long long u64;

__device__ int g_deg[NMAX];
__device__ int g_bcount[NUM_DST];
__device__ int g_bstart[NUM_DST];
__device__ int g_bcursor[NUM_DST];
__device__ int g_listcount;
__device__ int g_list[LISTCAP];
__device__ unsigned char g_spd[EMAX];
__device__ int g_sedge[EMAX];        // packed: src | (spd << 16), dst-bucket order
__device__ float g_q[NUM_DST * C];       // Q = x@Wq^T + bq (dst rows only)
__device__ float g_u[NUM_DST * H * C];   // pre-scaled by 1/sqrt(DH)*log2(e)
__device__ float g_c0[NUM_DST * H];      // pre-scaled by 1/sqrt(DH)*log2(e)
__device__ float g_agg[AGGSZ];       // un-normalized per-dst per-head x aggregation
__device__ float g_l[NUM_DST * H];   // softmax denominators
__device__ float g_outsmall[NUM_DST * C];

// ---- f32x2 packed helpers --------------------------------------------------
__device__ __forceinline__ u64 pack2(float lo, float hi) {
    u64 r; asm("mov.b64 %0, {%1, %2};" : "=l"(r) : "f"(lo), "f"(hi)); return r;
}
__device__ __forceinline__ void unpack2(u64 v, float& lo, float& hi) {
    asm("mov.b64 {%0, %1}, %2;" : "=f"(lo), "=f"(hi) : "l"(v));
}
__device__ __forceinline__ void fma2(u64& d, u64 a, u64 b) {
    asm("fma.rn.f32x2 %0, %1, %2, %3;" : "=l"(d) : "l"(a), "l"(b), "l"(d));
}

// ---------------------------------------------------------------------------
// K0: init deg, counters, agg/l accumulators; seed g_q with bq
__global__ void k_init(int n, const float* __restrict__ bq) {
    int i = blockIdx.x * blockDim.x + threadIdx.x;
    if (i < n) g_deg[i] = 0;
    if (i < AGGSZ) g_agg[i] = 0.f;
    if (i < NUM_DST * H) g_l[i] = 0.f;
    if (i < NUM_DST * C) g_q[i] = bq[i & (C - 1)];
    if (i < NUM_DST) g_bcount[i] = 0;
    if (i == 0) g_listcount = 0;
}

// ---------------------------------------------------------------------------
// K1: block-local histograms folded into g_bcount + out-degree + src<256 list
__global__ void k_hist(const int* __restrict__ src, const int* __restrict__ dst, int e) {
    __shared__ int hist[NUM_DST];
    int t = threadIdx.x;
    hist[t] = 0;
    __syncthreads();
    for (int i = blockIdx.x * blockDim.x + t; i < e; i += gridDim.x * blockDim.x) {
        int s = src[i], d = dst[i];
        atomicAdd(&g_deg[s], 1);
        atomicAdd(&hist[d], 1);
        if (s < NUM_DST) {
            int p = atomicAdd(&g_listcount, 1);
            if (p < LISTCAP) g_list[p] = i;
        }
    }
    __syncthreads();
    int c = hist[t];
    if (c) atomicAdd(&g_bcount[t], c);
}

// ---------------------------------------------------------------------------
// K2: fused single-block: (A) dst scan + deg fold, (B) smem-CSR BFS
__global__ void k_prebfs(const int* __restrict__ src, const int* __restrict__ dst) {
    __shared__ int tmp[NUM_DST];
    __shared__ unsigned F0[NUM_DST][8];
    __shared__ unsigned F1[NUM_DST][8];
    __shared__ unsigned short epk[BCAP];
    __shared__ unsigned char esp[BCAP];
    __shared__ unsigned char csrc[BCAP];
    __shared__ int cnt[NUM_DST];
    __shared__ int scan[NUM_DST];
    __shared__ int cur[NUM_DST];
    int t = threadIdx.x;

    // ---- phase A: exclusive scan of bucket totals ----
    int total = g_bcount[t];
    tmp[t] = total;
    __syncthreads();
    for (int off = 1; off < NUM_DST; off <<= 1) {
        int v = (t >= off) ? tmp[t - off] : 0;
        __syncthreads();
        tmp[t] += v;
        __syncthreads();
    }
    int excl = tmp[t] - total;
    g_bstart[t] = excl;
    g_bcursor[t] = excl;
    g_deg[t] += total;  // in-degree (all dst < 256)

    // ---- phase B: reverse-BFS (thread t owns frontier row t) ----
    #pragma unroll
    for (int w = 0; w < 8; w++)
        F0[t][w] = (w == (t >> 5)) ? (1u << (t & 31)) : 0u;
    cnt[t] = 0;
    __syncthreads();
    int lcnt = g_listcount;
    if (lcnt > LISTCAP) lcnt = LISTCAP;
    int scnt = lcnt < BCAP ? lcnt : BCAP;
    for (int i = t; i < scnt; i += 256) {
        int e = g_list[i];
        int s = src[e], d = dst[e];
        epk[i] = (unsigned short)(s | (d << 8));
        esp[i] = 4;
        atomicAdd(&cnt[d], 1);
    }
    for (int i = BCAP + t; i < lcnt; i += 256) g_spd[g_list[i]] = 4;
    __syncthreads();
    int myc = cnt[t];
    scan[t] = myc;
    __syncthreads();
    for (int off = 1; off < NUM_DST; off <<= 1) {
        int v = (t >= off) ? scan[t - off] : 0;
        __syncthreads();
        scan[t] += v;
        __syncthreads();
    }
    int base = scan[t] - myc;
    cur[t] = base;
    __syncthreads();
    for (int i = t; i < scnt; i += 256) {
        int p = epk[i];
        int d = p >> 8;
        int q = atomicAdd(&cur[d], 1);
        csrc[q] = (unsigned char)(p & 255);
    }
    __syncthreads();
    for (int k = 1; k <= 3; k++) {
        unsigned f0v = 0, f1v = 0, f2v = 0, f3v = 0, f4v = 0, f5v = 0, f6v = 0, f7v = 0;
        for (int j = base; j < base + myc; j++) {
            int s = csrc[j];
            f0v |= F0[s][0]; f1v |= F0[s][1]; f2v |= F0[s][2]; f3v |= F0[s][3];
            f4v |= F0[s][4]; f5v |= F0[s][5]; f6v |= F0[s][6]; f7v |= F0[s][7];
        }
        F1[t][0] = f0v; F1[t][1] = f1v; F1[t][2] = f2v; F1[t][3] = f3v;
        F1[t][4] = f4v; F1[t][5] = f5v; F1[t][6] = f6v; F1[t][7] = f7v;
        __syncthreads();
        for (int i = BCAP + t; i < lcnt; i += 256) {       // overflow path (unused)
            int e = g_list[i];
            int s = src[e], d = dst[e];
            #pragma unroll
            for (int w = 0; w < 8; w++) {
                unsigned v = F0[s][w];
                if (v) atomicOr(&F1[d][w], v);
            }
        }
        __syncthreads();
        for (int i = t; i < scnt; i += 256) {
            int p = epk[i];
            int s = p & 255, d = p >> 8;
            if (esp[i] == 4 && ((F1[s][d >> 5] >> (d & 31)) & 1u))
                esp[i] = (unsigned char)k;
        }
        for (int i = BCAP + t; i < lcnt; i += 256) {
            int e = g_list[i];
            int s = src[e], d = dst[e];
            if (g_spd[e] == 4 && ((F1[s][d >> 5] >> (d & 31)) & 1u))
                g_spd[e] = (unsigned char)k;
        }
        __syncthreads();
        #pragma unroll
        for (int w = 0; w < 8; w++) F0[t][w] = F1[t][w];
        __syncthreads();
    }
    for (int i = t; i < scnt; i += 256) g_spd[g_list[i]] = esp[i];
}

// ---------------------------------------------------------------------------
// K3a: Q += x[0:256] @ Wq^T  (split-K GEMM, 64x64x64 per block, atomic combine)
__global__ void k_q(const float* __restrict__ x, const float* __restrict__ Wq) {
    __shared__ float Xs[64][33];
    __shared__ float Ws[64][33];
    int t = threadIdx.x;
    int tx = t & 15, ty = t >> 4;
    int bm = blockIdx.y * 64, bn = blockIdx.x * 64;
    int kb = blockIdx.z * 64;
    float acc[4][4];
    #pragma unroll
    for (int i = 0; i < 4; i++)
        #pragma unroll
        for (int j = 0; j < 4; j++) acc[i][j] = 0.f;

    for (int k0 = kb; k0 < kb + 64; k0 += 32) {
        #pragma unroll
        for (int l = 0; l < 8; l++) {
            int idx = t + l * 256;
            int r = idx >> 5, c = idx & 31;
            Xs[r][c] = x[(bm + r) * C + k0 + c];
            Ws[r][c] = Wq[(bn + r) * C + k0 + c];
        }
        __syncthreads();
        #pragma unroll
        for (int kk = 0; kk < 32; kk++) {
            float av[4], bv[4];
            #pragma unroll
            for (int i = 0; i < 4; i++) av[i] = Xs[ty * 4 + i][kk];
            #pragma unroll
            for (int j = 0; j < 4; j++) bv[j] = Ws[tx * 4 + j][kk];
            #pragma unroll
            for (int i = 0; i < 4; i++)
                #pragma unroll
                for (int j = 0; j < 4; j++) acc[i][j] += av[i] * bv[j];
        }
        __syncthreads();
    }
    #pragma unroll
    for (int i = 0; i < 4; i++)
        #pragma unroll
        for (int j = 0; j < 4; j++)
            atomicAdd(&g_q[(bm + ty * 4 + i) * C + bn + tx * 4 + j], acc[i][j]);
}

// ---------------------------------------------------------------------------
// K3b: u[d][h][k] = (sum_j Q[d][h*32+j] * Wk[h*32+j][k]) * USCALE
__global__ void k_u(const float* __restrict__ Wk) {
    __shared__ float Qs[64][33];
    __shared__ float Ws[32][64];
    int t = threadIdx.x;
    int tx = t & 15, ty = t >> 4;
    int kx = blockIdx.x * 64, dy = blockIdx.y * 64, h = blockIdx.z;
    #pragma unroll
    for (int l = 0; l < 8; l++) {
        int idx = t + l * 256;
        int r = idx >> 5, c = idx & 31;
        Qs[r][c] = g_q[(dy + r) * C + h * 32 + c];
    }
    #pragma unroll
    for (int l = 0; l < 8; l++) {
        int idx = t + l * 256;
        int r = idx >> 6, c = idx & 63;
        Ws[r][c] = Wk[(h * 32 + r) * C + kx + c];
    }
    __syncthreads();
    float acc[4][4];
    #pragma unroll
    for (int i = 0; i < 4; i++)
        #pragma unroll
        for (int j = 0; j < 4; j++) acc[i][j] = 0.f;
    #pragma unroll
    for (int kk = 0; kk < 32; kk++) {
        float av[4], bv[4];
        #pragma unroll
        for (int i = 0; i < 4; i++) av[i] = Qs[ty * 4 + i][kk];
        #pragma unroll
        for (int j = 0; j < 4; j++) bv[j] = Ws[kk][tx * 4 + j];
        #pragma unroll
        for (int i = 0; i < 4; i++)
            #pragma unroll
            for (int j = 0; j < 4; j++) acc[i][j] += av[i] * bv[j];
    }
    #pragma unroll
    for (int i = 0; i < 4; i++)
        #pragma unroll
        for (int j = 0; j < 4; j++)
            g_u[(dy + ty * 4 + i) * (H * C) + h * C + kx + tx * 4 + j] = acc[i][j] * USCALE;
}

// ---------------------------------------------------------------------------
// K3c: c0[d][h] = (sum_j Q[d][h*32+j] * bk[h*32+j]) * USCALE
__global__ void k_c0(const float* __restrict__ bk) {
    __shared__ float bks[32];
    int h = blockIdx.x, d = threadIdx.x;
    if (d < 32) bks[d] = bk[h * 32 + d];
    __syncthreads();
    float s = 0.f;
    #pragma unroll
    for (int j = 0; j < 32; j++) s += g_q[d * C + h * 32 + j] * bks[j];
    g_c0[d * H + h] = s * USCALE;
}

// ---------------------------------------------------------------------------
// K4: reservation-based scatter — local hist, one global reserve per dst,
// then scatter through smem cursors. Packs (src, spd) into one int.
__global__ void k_scatter(const int* __restrict__ src, const int* __restrict__ dst, int e) {
    __shared__ int hist[NUM_DST];
    __shared__ int cur[NUM_DST];
    int t = threadIdx.x;
    hist[t] = 0;
    __syncthreads();
    for (int i = blockIdx.x * blockDim.x + t; i < e; i += gridDim.x * blockDim.x)
        atomicAdd(&hist[dst[i]], 1);
    __syncthreads();
    int c = hist[t];
    if (c) cur[t] = atomicAdd(&g_bcursor[t], c);
    __syncthreads();
    for (int i = blockIdx.x * blockDim.x + t; i < e; i += gridDim.x * blockDim.x) {
        int s = src[i], d = dst[i];
        int p = atomicAdd(&cur[d], 1);
        int sp = (s < NUM_DST) ? (int)g_spd[i] : 4;
        g_sedge[p] = s | (sp << 16);   // s < 50000 < 2^16
    }
}

// ---------------------------------------------------------------------------
// K5: fused attention partials — HEAD-SPLIT WARP PAIRS + 2-EDGE INTERLEAVE.
// 128 thr / 4 warps, occ 4. Warp parity picks heads 0-3 vs 4-7 (32 u-regs +
// 32 acc-regs); warp pair shares an edge stream. Two independent edge bodies
// per loop iteration (MLP 2 on the x gathers, interleaved chains).
__global__ __launch_bounds__(128, 4)
void k_attn(const float* __restrict__ x, const float* __restrict__ spd_w) {
    int blk = blockIdx.x;
    int d = blk >> 3, seg = blk & 7;
    int t = threadIdx.x, lane = t & 31, wp = t >> 5;
    int par = wp & 1;                 // heads par*4 .. par*4+3
    int wpair = wp >> 1;              // edge stream 0/1
    __shared__ __align__(16) float scratch[2][4 * C];  // 8 KB, maps 1:1 to g_agg rows
    __shared__ float csw[5 * H];
    __shared__ float lsh[16];

    if (t < 40) csw[t] = g_c0[d * H + (t & 7)] + spd_w[t] * LOG2E;

    // u for this warp's 4 heads: 4 x 8 channels per lane (32 regs)
    u64 ur[4][4];
    const float* ubase = g_u + d * (H * C) + par * 4 * C + lane * 8;
    #pragma unroll
    for (int h4 = 0; h4 < 4; h4++) {
        ulonglong2 p0 = *(const ulonglong2*)(ubase + h4 * C);
        ulonglong2 p1 = *(const ulonglong2*)(ubase + h4 * C + 4);
        ur[h4][0] = p0.x; ur[h4][1] = p0.y; ur[h4][2] = p1.x; ur[h4][3] = p1.y;
    }
    __syncthreads();

    int s0 = g_bstart[d], cnt = g_bcount[d];
    int b0 = s0 + (cnt * seg) / SPLIT;
    int b1 = s0 + (cnt * (seg + 1)) / SPLIT;

    int lh = (lane >> 3) & 3;             // local head owned after butterfly
    int myh = par * 4 + lh;
    unsigned b4 = (lane >> 4) & 1, b3 = (lane >> 3) & 1;

    u64 acc2[4][4];
    #pragma unroll
    for (int h4 = 0; h4 < 4; h4++)
        #pragma unroll
        for (int j = 0; j < 4; j++) acc2[h4][j] = 0ull;
    float lsum = 0.f;

    // 2 edges per iteration on this pair's stream (stride 2): i and i+2
    for (int i = b0 + wpair; i < b1; i += 4) {
        int i1 = i + 2;
        bool has1 = (i1 < b1);
        int v0 = g_sedge[i];
        int v1 = has1 ? g_sedge[i1] : 0;
        // both x rows issue back-to-back (MLP 2)
        const float4* xr0 = (const float4*)(x + (v0 & 0xFFFF) * C) + lane * 2;
        const float4* xr1 = (const float4*)(x + (v1 & 0xFFFF) * C) + lane * 2;
        float4 a0 = xr0[0], c0 = xr0[1];
        float4 a1, c1;
        if (has1) { a1 = xr1[0]; c1 = xr1[1]; }

        // ---- edge 0 body ----
        u64 y0[4];
        y0[0] = pack2(a0.x, a0.y); y0[1] = pack2(a0.z, a0.w);
        y0[2] = pack2(c0.x, c0.y); y0[3] = pack2(c0.z, c0.w);
        float p0[4];
        #pragma unroll
        for (int h4 = 0; h4 < 4; h4++) {
            u64 q2 = 0ull;
            fma2(q2, y0[0], ur[h4][0]);
            fma2(q2, y0[1], ur[h4][1]);
            fma2(q2, y0[2], ur[h4][2]);
            fma2(q2, y0[3], ur[h4][3]);
            float lo, hi; unpack2(q2, lo, hi);
            p0[h4] = lo + hi;
        }
        // ---- edge 1 dot (interleaves with edge 0 reduction) ----
        u64 y1[4];
        float p1[4];
        if (has1) {
            y1[0] = pack2(a1.x, a1.y); y1[1] = pack2(a1.z, a1.w);
            y1[2] = pack2(c1.x, c1.y); y1[3] = pack2(c1.z, c1.w);
            #pragma unroll
            for (int h4 = 0; h4 < 4; h4++) {
                u64 q2 = 0ull;
                fma2(q2, y1[0], ur[h4][0]);
                fma2(q2, y1[1], ur[h4][1]);
                fma2(q2, y1[2], ur[h4][2]);
                fma2(q2, y1[3], ur[h4][3]);
                float lo, hi; unpack2(q2, lo, hi);
                p1[h4] = lo + hi;
            }
        }

        // ---- butterflies (two independent 5-shfl chains) ----
        float r0a, r1a;
        {
            float m0[2], m1[2];
            #pragma unroll
            for (int j = 0; j < 2; j++) {
                float mine = b4 ? p0[j + 2] : p0[j];
                float send = b4 ? p0[j] : p0[j + 2];
                m0[j] = mine + __shfl_xor_sync(0xffffffffu, send, 16);
            }
            if (has1) {
                #pragma unroll
                for (int j = 0; j < 2; j++) {
                    float mine = b4 ? p1[j + 2] : p1[j];
                    float send = b4 ? p1[j] : p1[j + 2];
                    m1[j] = mine + __shfl_xor_sync(0xffffffffu, send, 16);
                }
            }
            {
                float mine = b3 ? m0[1] : m0[0];
                float send = b3 ? m0[0] : m0[1];
                r0a = mine + __shfl_xor_sync(0xffffffffu, send, 8);
            }
            if (has1) {
                float mine = b3 ? m1[1] : m1[0];
                float send = b3 ? m1[0] : m1[1];
                r1a = mine + __shfl_xor_sync(0xffffffffu, send, 8);
            }
            r0a += __shfl_xor_sync(0xffffffffu, r0a, 4);
            if (has1) r1a += __shfl_xor_sync(0xffffffffu, r1a, 4);
            r0a += __shfl_xor_sync(0xffffffffu, r0a, 2);
            if (has1) r1a += __shfl_xor_sync(0xffffffffu, r1a, 2);
            r0a += __shfl_xor_sync(0xffffffffu, r0a, 1);
            if (has1) r1a += __shfl_xor_sync(0xffffffffu, r1a, 1);
        }

        int sp0 = v0 >> 16;
        float w0 = exp2f(r0a + csw[sp0 * H + myh]);
        lsum += w0;
        #pragma unroll
        for (int h4 = 0; h4 < 4; h4++) {
            float wh = __shfl_sync(0xffffffffu, w0, h4 * 8);
            u64 w2 = pack2(wh, wh);
            fma2(acc2[h4][0], w2, y0[0]);
            fma2(acc2[h4][1], w2, y0[1]);
            fma2(acc2[h4][2], w2, y0[2]);
            fma2(acc2[h4][3], w2, y0[3]);
        }
        if (has1) {
            int sp1 = v1 >> 16;
            float w1 = exp2f(r1a + csw[sp1 * H + myh]);
            lsum += w1;
            #pragma unroll
            for (int h4 = 0; h4 < 4; h4++) {
                float wh = __shfl_sync(0xffffffffu, w1, h4 * 8);
                u64 w2 = pack2(wh, wh);
                fma2(acc2[h4][0], w2, y1[0]);
                fma2(acc2[h4][1], w2, y1[1]);
                fma2(acc2[h4][2], w2, y1[2]);
                fma2(acc2[h4][3], w2, y1[3]);
            }
        }
    }

    // epilogue: lsh[wp*4+lh]; warps 2,3 store; warps 0,1 add; REDG combine
    if ((lane & 7) == 0) lsh[wp * 4 + lh] = lsum;
    if (wp >= 2) {
        #pragma unroll
        for (int h4 = 0; h4 < 4; h4++) {
            u64* dp = (u64*)&scratch[par][h4 * C + lane * 8];
            dp[0] = acc2[h4][0]; dp[1] = acc2[h4][1];
            dp[2] = acc2[h4][2]; dp[3] = acc2[h4][3];
        }
    }
    __syncthreads();
    if (wp < 2) {
        u64 one = pack2(1.f, 1.f);
        #pragma unroll
        for (int h4 = 0; h4 < 4; h4++) {
            u64* dp = (u64*)&scratch[par][h4 * C + lane * 8];
            u64 s0q = dp[0], s1q = dp[1], s2q = dp[2], s3q = dp[3];
            fma2(s0q, one, acc2[h4][0]);
            fma2(s1q, one, acc2[h4][1]);
            fma2(s2q, one, acc2[h4][2]);
            fma2(s3q, one, acc2[h4][3]);
            dp[0] = s0q; dp[1] = s1q; dp[2] = s2q; dp[3] = s3q;
        }
    }
    __syncthreads();
    // scratch flat [2][4*C] == g_agg rows [heads 0-3][heads 4-7] contiguously
    float* gbase = g_agg + d * (H * C);
    const float* sflat = &scratch[0][0];
    for (int idx = t; idx < H * C; idx += 128)
        atomicAdd(&gbase[idx], sflat[idx]);
    if (t < H) atomicAdd(&g_l[d * H + t], lsh[t] + lsh[8 + t]);
}

// ---------------------------------------------------------------------------
// K6: normalize + V projection: out[c] = (agg[c/32]/L) . Wv[c,:] + bv[c]
__global__ void k_vproj(const float* __restrict__ Wv, const float* __restrict__ bv) {
    int d = blockIdx.x;
    int t = threadIdx.x, lane = t & 31, wp = t >> 5;
    __shared__ __align__(16) float agg[H * C];
    __shared__ float Linv[H];
    if (g_bcount[d] == 0) {
        g_outsmall[d * C + t] = 0.f;
        return;
    }
    if (t < H) Linv[t] = 1.f / g_l[d * H + t];
    __syncthreads();
    for (int idx = t; idx < H * C; idx += 256)
        agg[idx] = g_agg[d * (H * C) + idx] * Linv[idx >> 8];
    __syncthreads();
    for (int r = 0; r < 32; r++) {
        int c = wp * 32 + r;
        int h = c >> 5;
        const float4* wr = (const float4*)(Wv + c * C) + lane * 2;
        float4 wa = wr[0], wb = wr[1];
        const float* ar = &agg[h * C + lane * 8];
        float pacc = wa.x * ar[0] + wa.y * ar[1] + wa.z * ar[2] + wa.w * ar[3]
                   + wb.x * ar[4] + wb.y * ar[5] + wb.z * ar[6] + wb.w * ar[7];
        #pragma unroll
        for (int o = 16; o; o >>= 1) pacc += __shfl_xor_sync(0xffffffffu, pacc, o);
        if (lane == 0) g_outsmall[d * C + c] = pacc + bv[c];
    }
}

// ---------------------------------------------------------------------------
// K7: residual + degree + LayerNorm, one warp per row
__global__ void k_ln(const float* __restrict__ x,
                     const float* __restrict__ gamma, const float* __restrict__ beta,
                     float* __restrict__ out, int n) {
    int row = blockIdx.x * 8 + (threadIdx.x >> 5);
    int lane = threadIdx.x & 31;
    if (row >= n) return;
    const float* xr = x + (size_t)row * C + lane * 8;
    float4 a = *(const float4*)(xr);
    float4 b = *(const float4*)(xr + 4);
    float v[8] = {a.x, a.y, a.z, a.w, b.x, b.y, b.z, b.w};
    float degf = (float)g_deg[row];
    #pragma unroll
    for (int j = 0; j < 8; j++) v[j] += degf;
    if (row < NUM_DST) {
        const float* orow = g_outsmall + row * C + lane * 8;
        float4 oa = *(const float4*)(orow);
        float4 ob = *(const float4*)(orow + 4);
        v[0] += oa.x; v[1] += oa.y; v[2] += oa.z; v[3] += oa.w;
        v[4] += ob.x; v[5] += ob.y; v[6] += ob.z; v[7] += ob.w;
    }
    float s = 0.f;
    #pragma unroll
    for (int j = 0; j < 8; j++) s += v[j];
    #pragma unroll
    for (int o = 16; o; o >>= 1) s += __shfl_xor_sync(0xffffffffu, s, o);
    float mu = s * (1.f / C);
    float q = 0.f;
    #pragma unroll
    for (int j = 0; j < 8; j++) { float dd = v[j] - mu; q += dd * dd; }
    #pragma unroll
    for (int o = 16; o; o >>= 1) q += __shfl_xor_sync(0xffffffffu, q, o);
    float rstd = rsqrtf(q * (1.f / C) + LN_EPS);
    const float* gr = gamma + lane * 8;
    const float* br = beta + lane * 8;
    float4 g1 = *(const float4*)(gr);
    float4 g2 = *(const float4*)(gr + 4);
    float4 b1 = *(const float4*)(br);
    float4 b2 = *(const float4*)(br + 4);
    float gv[8] = {g1.x, g1.y, g1.z, g1.w, g2.x, g2.y, g2.z, g2.w};
    float bvv[8] = {b1.x, b1.y, b1.z, b1.w, b2.x, b2.y, b2.z, b2.w};
    float o[8];
    #pragma unroll
    for (int j = 0; j < 8; j++) o[j] = (v[j] - mu) * rstd * gv[j] + bvv[j];
    float* orow = out + (size_t)row * C + lane * 8;
    *(float4*)(orow) = make_float4(o[0], o[1], o[2], o[3]);
    *(float4*)(orow + 4) = make_float4(o[4], o[5], o[6], o[7]);
}

// ---------------------------------------------------------------------------
extern "C" void kernel_launch(void* const* d_in, const int* in_sizes, int n_in,
                              void* d_out, int out_size) {
    const float* x     = (const float*)d_in[0];
    const int*   src   = (const int*)d_in[1];
    const int*   dst   = (const int*)d_in[2];
    const float* Wq    = (const float*)d_in[3];
    const float* bq    = (const float*)d_in[4];
    const float* Wk    = (const float*)d_in[5];
    const float* bk    = (const float*)d_in[6];
    const float* Wv    = (const float*)d_in[7];
    const float* bv    = (const float*)d_in[8];
    const float* spd_w = (const float*)d_in[9];
    const float* gamma = (const float*)d_in[10];
    const float* beta  = (const float*)d_in[11];
    float* out = (float*)d_out;

    int n = in_sizes[0] / C;
    int e = in_sizes[1];
    int initN = (AGGSZ > n) ? AGGSZ : n;

    k_init<<<(initN + 255) / 256, 256>>>(n, bq);
    k_hist<<<HB, 256>>>(src, dst, e);
    k_prebfs<<<1, 256>>>(src, dst);
    k_q<<<dim3(4, 4, 4), 256>>>(x, Wq);            // 4th launch -> ncu capture
    k_u<<<dim3(4, 4, 8), 256>>>(Wk);
    k_c0<<<H, 256>>>(bk);
    k_scatter<<<HB, 256>>>(src, dst, e);
    k_attn<<<NUM_DST * SPLIT, 128>>>(x, spd_w);
    k_vproj<<<NUM_DST, 256>>>(Wv, bv);
    k_ln<<<(n + 7) / 8, 256>>>(x, gamma, beta, out, n);
}

// round 17
// speedup vs baseline: 1.1752x; 1.1752x over previous
#include <cuda_runtime.h>

#define C 256
#define H 8
#define NUM_DST 256
#define NMAX 50000
#define EMAX 300000
#define LISTCAP 8192
#define BCAP 4096         // smem-resident BFS edge cap (expected ~1536)
#define HB 256            // histogram/scatter blocks
#define INV_SQRT_DH 0.17677669529663687f
#define LOG2E 1.4426950408889634f
#define USCALE (INV_SQRT_DH * LOG2E)
#define LN_EPS 1e-5f
#define SPLIT 4           // blocks per dst bucket
#define AGGSZ (NUM_DST * H * C)   // 524288

typedef unsigned long long u64;

__device__ int g_deg[NMAX];
__device__ int g_bcount[NUM_DST];
__device__ int g_bstart[NUM_DST];
__device__ int g_bcursor[NUM_DST];
__device__ int g_listcount;
__device__ int g_list[LISTCAP];
__device__ unsigned char g_spd[EMAX];
__device__ int g_sedge[EMAX];        // packed: src | (spd << 16), dst-bucket order
__device__ float g_q[NUM_DST * C];       // Q = x@Wq^T + bq (dst rows only)
__device__ float g_u[NUM_DST * H * C];   // pre-scaled by 1/sqrt(DH)*log2(e)
__device__ float g_c0[NUM_DST * H];      // pre-scaled by 1/sqrt(DH)*log2(e)
__device__ float g_agg[AGGSZ];       // un-normalized per-dst per-head x aggregation
__device__ float g_l[NUM_DST * H];   // softmax denominators
__device__ float g_outsmall[NUM_DST * C];

// ---- f32x2 packed helpers --------------------------------------------------
__device__ __forceinline__ u64 pack2(float lo, float hi) {
    u64 r; asm("mov.b64 %0, {%1, %2};" : "=l"(r) : "f"(lo), "f"(hi)); return r;
}
__device__ __forceinline__ void unpack2(u64 v, float& lo, float& hi) {
    asm("mov.b64 {%0, %1}, %2;" : "=f"(lo), "=f"(hi) : "l"(v));
}
__device__ __forceinline__ void fma2(u64& d, u64 a, u64 b) {
    asm("fma.rn.f32x2 %0, %1, %2, %3;" : "=l"(d) : "l"(a), "l"(b), "l"(d));
}

// ---------------------------------------------------------------------------
// K0: init deg, counters, agg/l accumulators; seed g_q with bq
__global__ void k_init(int n, const float* __restrict__ bq) {
    int i = blockIdx.x * blockDim.x + threadIdx.x;
    if (i < n) g_deg[i] = 0;
    if (i < AGGSZ) g_agg[i] = 0.f;
    if (i < NUM_DST * H) g_l[i] = 0.f;
    if (i < NUM_DST * C) g_q[i] = bq[i & (C - 1)];
    if (i < NUM_DST) g_bcount[i] = 0;
    if (i == 0) g_listcount = 0;
}

// ---------------------------------------------------------------------------
// K1: block-local histograms folded into g_bcount + out-degree + src<256 list
__global__ void k_hist(const int* __restrict__ src, const int* __restrict__ dst, int e) {
    __shared__ int hist[NUM_DST];
    int t = threadIdx.x;
    hist[t] = 0;
    __syncthreads();
    for (int i = blockIdx.x * blockDim.x + t; i < e; i += gridDim.x * blockDim.x) {
        int s = src[i], d = dst[i];
        atomicAdd(&g_deg[s], 1);
        atomicAdd(&hist[d], 1);
        if (s < NUM_DST) {
            int p = atomicAdd(&g_listcount, 1);
            if (p < LISTCAP) g_list[p] = i;
        }
    }
    __syncthreads();
    int c = hist[t];
    if (c) atomicAdd(&g_bcount[t], c);
}

// ---------------------------------------------------------------------------
// K2: fused single-block: (A) dst scan + deg fold, (B) smem-CSR BFS
__global__ void k_prebfs(const int* __restrict__ src, const int* __restrict__ dst) {
    __shared__ int tmp[NUM_DST];
    __shared__ unsigned F0[NUM_DST][8];
    __shared__ unsigned F1[NUM_DST][8];
    __shared__ unsigned short epk[BCAP];
    __shared__ unsigned char esp[BCAP];
    __shared__ unsigned char csrc[BCAP];
    __shared__ int cnt[NUM_DST];
    __shared__ int scan[NUM_DST];
    __shared__ int cur[NUM_DST];
    int t = threadIdx.x;

    // ---- phase A: exclusive scan of bucket totals ----
    int total = g_bcount[t];
    tmp[t] = total;
    __syncthreads();
    for (int off = 1; off < NUM_DST; off <<= 1) {
        int v = (t >= off) ? tmp[t - off] : 0;
        __syncthreads();
        tmp[t] += v;
        __syncthreads();
    }
    int excl = tmp[t] - total;
    g_bstart[t] = excl;
    g_bcursor[t] = excl;
    g_deg[t] += total;  // in-degree (all dst < 256)

    // ---- phase B: reverse-BFS (thread t owns frontier row t) ----
    #pragma unroll
    for (int w = 0; w < 8; w++)
        F0[t][w] = (w == (t >> 5)) ? (1u << (t & 31)) : 0u;
    cnt[t] = 0;
    __syncthreads();
    int lcnt = g_listcount;
    if (lcnt > LISTCAP) lcnt = LISTCAP;
    int scnt = lcnt < BCAP ? lcnt : BCAP;
    for (int i = t; i < scnt; i += 256) {
        int e = g_list[i];
        int s = src[e], d = dst[e];
        epk[i] = (unsigned short)(s | (d << 8));
        esp[i] = 4;
        atomicAdd(&cnt[d], 1);
    }
    for (int i = BCAP + t; i < lcnt; i += 256) g_spd[g_list[i]] = 4;
    __syncthreads();
    int myc = cnt[t];
    scan[t] = myc;
    __syncthreads();
    for (int off = 1; off < NUM_DST; off <<= 1) {
        int v = (t >= off) ? scan[t - off] : 0;
        __syncthreads();
        scan[t] += v;
        __syncthreads();
    }
    int base = scan[t] - myc;
    cur[t] = base;
    __syncthreads();
    for (int i = t; i < scnt; i += 256) {
        int p = epk[i];
        int d = p >> 8;
        int q = atomicAdd(&cur[d], 1);
        csrc[q] = (unsigned char)(p & 255);
    }
    __syncthreads();
    for (int k = 1; k <= 3; k++) {
        unsigned f0v = 0, f1v = 0, f2v = 0, f3v = 0, f4v = 0, f5v = 0, f6v = 0, f7v = 0;
        for (int j = base; j < base + myc; j++) {
            int s = csrc[j];
            f0v |= F0[s][0]; f1v |= F0[s][1]; f2v |= F0[s][2]; f3v |= F0[s][3];
            f4v |= F0[s][4]; f5v |= F0[s][5]; f6v |= F0[s][6]; f7v |= F0[s][7];
        }
        F1[t][0] = f0v; F1[t][1] = f1v; F1[t][2] = f2v; F1[t][3] = f3v;
        F1[t][4] = f4v; F1[t][5] = f5v; F1[t][6] = f6v; F1[t][7] = f7v;
        __syncthreads();
        for (int i = BCAP + t; i < lcnt; i += 256) {       // overflow path (unused)
            int e = g_list[i];
            int s = src[e], d = dst[e];
            #pragma unroll
            for (int w = 0; w < 8; w++) {
                unsigned v = F0[s][w];
                if (v) atomicOr(&F1[d][w], v);
            }
        }
        __syncthreads();
        for (int i = t; i < scnt; i += 256) {
            int p = epk[i];
            int s = p & 255, d = p >> 8;
            if (esp[i] == 4 && ((F1[s][d >> 5] >> (d & 31)) & 1u))
                esp[i] = (unsigned char)k;
        }
        for (int i = BCAP + t; i < lcnt; i += 256) {
            int e = g_list[i];
            int s = src[e], d = dst[e];
            if (g_spd[e] == 4 && ((F1[s][d >> 5] >> (d & 31)) & 1u))
                g_spd[e] = (unsigned char)k;
        }
        __syncthreads();
        #pragma unroll
        for (int w = 0; w < 8; w++) F0[t][w] = F1[t][w];
        __syncthreads();
    }
    for (int i = t; i < scnt; i += 256) g_spd[g_list[i]] = esp[i];
}

// ---------------------------------------------------------------------------
// K3a: Q += x[0:256] @ Wq^T  (split-K GEMM, 64x64x64 per block, atomic combine)
__global__ void k_q(const float* __restrict__ x, const float* __restrict__ Wq) {
    __shared__ float Xs[64][33];
    __shared__ float Ws[64][33];
    int t = threadIdx.x;
    int tx = t & 15, ty = t >> 4;
    int bm = blockIdx.y * 64, bn = blockIdx.x * 64;
    int kb = blockIdx.z * 64;
    float acc[4][4];
    #pragma unroll
    for (int i = 0; i < 4; i++)
        #pragma unroll
        for (int j = 0; j < 4; j++) acc[i][j] = 0.f;

    for (int k0 = kb; k0 < kb + 64; k0 += 32) {
        #pragma unroll
        for (int l = 0; l < 8; l++) {
            int idx = t + l * 256;
            int r = idx >> 5, c = idx & 31;
            Xs[r][c] = x[(bm + r) * C + k0 + c];
            Ws[r][c] = Wq[(bn + r) * C + k0 + c];
        }
        __syncthreads();
        #pragma unroll
        for (int kk = 0; kk < 32; kk++) {
            float av[4], bv[4];
            #pragma unroll
            for (int i = 0; i < 4; i++) av[i] = Xs[ty * 4 + i][kk];
            #pragma unroll
            for (int j = 0; j < 4; j++) bv[j] = Ws[tx * 4 + j][kk];
            #pragma unroll
            for (int i = 0; i < 4; i++)
                #pragma unroll
                for (int j = 0; j < 4; j++) acc[i][j] += av[i] * bv[j];
        }
        __syncthreads();
    }
    #pragma unroll
    for (int i = 0; i < 4; i++)
        #pragma unroll
        for (int j = 0; j < 4; j++)
            atomicAdd(&g_q[(bm + ty * 4 + i) * C + bn + tx * 4 + j], acc[i][j]);
}

// ---------------------------------------------------------------------------
// K3b: u[d][h][k] = (sum_j Q[d][h*32+j] * Wk[h*32+j][k]) * USCALE
// kx==0 blocks also compute c0[d][h] from the smem-resident Q tile.
__global__ void k_u(const float* __restrict__ Wk, const float* __restrict__ bk) {
    __shared__ float Qs[64][33];
    __shared__ float Ws[32][64];
    int t = threadIdx.x;
    int tx = t & 15, ty = t >> 4;
    int kx = blockIdx.x * 64, dy = blockIdx.y * 64, h = blockIdx.z;
    #pragma unroll
    for (int l = 0; l < 8; l++) {
        int idx = t + l * 256;
        int r = idx >> 5, c = idx & 31;
        Qs[r][c] = g_q[(dy + r) * C + h * 32 + c];
    }
    #pragma unroll
    for (int l = 0; l < 8; l++) {
        int idx = t + l * 256;
        int r = idx >> 6, c = idx & 63;
        Ws[r][c] = Wk[(h * 32 + r) * C + kx + c];
    }
    __syncthreads();
    float acc[4][4];
    #pragma unroll
    for (int i = 0; i < 4; i++)
        #pragma unroll
        for (int j = 0; j < 4; j++) acc[i][j] = 0.f;
    #pragma unroll
    for (int kk = 0; kk < 32; kk++) {
        float av[4], bv[4];
        #pragma unroll
        for (int i = 0; i < 4; i++) av[i] = Qs[ty * 4 + i][kk];
        #pragma unroll
        for (int j = 0; j < 4; j++) bv[j] = Ws[kk][tx * 4 + j];
        #pragma unroll
        for (int i = 0; i < 4; i++)
            #pragma unroll
            for (int j = 0; j < 4; j++) acc[i][j] += av[i] * bv[j];
    }
    #pragma unroll
    for (int i = 0; i < 4; i++)
        #pragma unroll
        for (int j = 0; j < 4; j++)
            g_u[(dy + ty * 4 + i) * (H * C) + h * C + kx + tx * 4 + j] = acc[i][j] * USCALE;

    // fold c0 into the kx==0 blocks (Q tile already in smem)
    if (blockIdx.x == 0 && t < 64) {
        float s = 0.f;
        #pragma unroll
        for (int j = 0; j < 32; j++) s += Qs[t][j] * bk[h * 32 + j];
        g_c0[(dy + t) * H + h] = s * USCALE;
    }
}

// ---------------------------------------------------------------------------
// K4: reservation-based scatter — local hist, one global reserve per dst,
// then scatter through smem cursors. Packs (src, spd) into one int.
__global__ void k_scatter(const int* __restrict__ src, const int* __restrict__ dst, int e) {
    __shared__ int hist[NUM_DST];
    __shared__ int cur[NUM_DST];
    int t = threadIdx.x;
    hist[t] = 0;
    __syncthreads();
    for (int i = blockIdx.x * blockDim.x + t; i < e; i += gridDim.x * blockDim.x)
        atomicAdd(&hist[dst[i]], 1);
    __syncthreads();
    int c = hist[t];
    if (c) cur[t] = atomicAdd(&g_bcursor[t], c);
    __syncthreads();
    for (int i = blockIdx.x * blockDim.x + t; i < e; i += gridDim.x * blockDim.x) {
        int s = src[i], d = dst[i];
        int p = atomicAdd(&cur[d], 1);
        int sp = (s < NUM_DST) ? (int)g_spd[i] : 4;
        g_sedge[p] = s | (sp << 16);   // s < 50000 < 2^16
    }
}

// ---------------------------------------------------------------------------
// K5: fused attention partials — HEAD-SPLIT WARP PAIRS (R15, best measured).
// 128 thr / 4 warps, occ 4. Warp parity picks heads 0-3 vs 4-7 (32 u-regs +
// 32 acc-regs per lane); warp pair (2w,2w+1) shares an edge stream (2nd
// x-load hits L1). 5-shfl butterfly; parity-partitioned smem epilogue.
__global__ __launch_bounds__(128, 4)
void k_attn(const float* __restrict__ x, const float* __restrict__ spd_w) {
    int blk = blockIdx.x;
    int d = blk >> 2, seg = blk & 3;
    int t = threadIdx.x, lane = t & 31, wp = t >> 5;
    int par = wp & 1;                 // heads par*4 .. par*4+3
    int wpair = wp >> 1;              // edge stream 0/1
    __shared__ __align__(16) float scratch[2][4 * C];  // 8 KB, maps 1:1 to g_agg rows
    __shared__ float csw[5 * H];
    __shared__ float lsh[16];

    if (t < 40) csw[t] = g_c0[d * H + (t & 7)] + spd_w[t] * LOG2E;

    // u for this warp's 4 heads: 4 x 8 channels per lane (32 regs)
    u64 ur[4][4];
    const float* ubase = g_u + d * (H * C) + par * 4 * C + lane * 8;
    #pragma unroll
    for (int h4 = 0; h4 < 4; h4++) {
        ulonglong2 p0 = *(const ulonglong2*)(ubase + h4 * C);
        ulonglong2 p1 = *(const ulonglong2*)(ubase + h4 * C + 4);
        ur[h4][0] = p0.x; ur[h4][1] = p0.y; ur[h4][2] = p1.x; ur[h4][3] = p1.y;
    }
    __syncthreads();

    int s0 = g_bstart[d], cnt = g_bcount[d];
    int b0 = s0 + (cnt * seg) / SPLIT;
    int b1 = s0 + (cnt * (seg + 1)) / SPLIT;

    int lh = (lane >> 3) & 3;             // local head owned after butterfly
    int myh = par * 4 + lh;
    unsigned b4 = (lane >> 4) & 1, b3 = (lane >> 3) & 1;

    u64 acc2[4][4];
    #pragma unroll
    for (int h4 = 0; h4 < 4; h4++)
        #pragma unroll
        for (int j = 0; j < 4; j++) acc2[h4][j] = 0ull;
    float lsum = 0.f;

    // software pipeline over this pair's stream (stride 2)
    int i = b0 + wpair;
    int v0 = (i < b1) ? g_sedge[i] : 0;
    const float4* xr0 = (const float4*)(x + (v0 & 0xFFFF) * C) + lane * 2;
    float4 a, b;
    if (i < b1) { a = xr0[0]; b = xr0[1]; }

    for (; i < b1; i += 2) {
        int v1 = ((i + 2) < b1) ? g_sedge[i + 2] : 0;
        const float4* xr1 = (const float4*)(x + (v1 & 0xFFFF) * C) + lane * 2;
        float4 na, nb;
        if (i + 2 < b1) { na = xr1[0]; nb = xr1[1]; }
        int sp = v0 >> 16;

        u64 xv2[4];
        xv2[0] = pack2(a.x, a.y); xv2[1] = pack2(a.z, a.w);
        xv2[2] = pack2(b.x, b.y); xv2[3] = pack2(b.z, b.w);

        // dots for this warp's 4 heads (16 fma2)
        float p[4];
        #pragma unroll
        for (int h4 = 0; h4 < 4; h4++) {
            u64 q2 = 0ull;
            fma2(q2, xv2[0], ur[h4][0]);
            fma2(q2, xv2[1], ur[h4][1]);
            fma2(q2, xv2[2], ur[h4][2]);
            fma2(q2, xv2[3], ur[h4][3]);
            float lo, hi; unpack2(q2, lo, hi);
            p[h4] = lo + hi;
        }

        // 5-shfl head-folding butterfly (4 heads -> one per 8-lane group)
        float r2[2];
        #pragma unroll
        for (int j = 0; j < 2; j++) {
            float mine = b4 ? p[j + 2] : p[j];
            float send = b4 ? p[j] : p[j + 2];
            r2[j] = mine + __shfl_xor_sync(0xffffffffu, send, 16);
        }
        float r1;
        {
            float mine = b3 ? r2[1] : r2[0];
            float send = b3 ? r2[0] : r2[1];
            r1 = mine + __shfl_xor_sync(0xffffffffu, send, 8);
        }
        r1 += __shfl_xor_sync(0xffffffffu, r1, 4);
        r1 += __shfl_xor_sync(0xffffffffu, r1, 2);
        r1 += __shfl_xor_sync(0xffffffffu, r1, 1);
        // lane holds full score for head myh = par*4 + (lane>>3)&3

        float wv = exp2f(r1 + csw[sp * H + myh]);   // pre-scaled by log2e
        lsum += wv;

        #pragma unroll
        for (int h4 = 0; h4 < 4; h4++) {
            float wh = __shfl_sync(0xffffffffu, wv, h4 * 8);
            u64 w2 = pack2(wh, wh);
            fma2(acc2[h4][0], w2, xv2[0]);
            fma2(acc2[h4][1], w2, xv2[1]);
            fma2(acc2[h4][2], w2, xv2[2]);
            fma2(acc2[h4][3], w2, xv2[3]);
        }

        v0 = v1; a = na; b = nb;
    }

    // epilogue: lsh[wp*4+lh]; warps 2,3 store; warps 0,1 add; REDG combine
    if ((lane & 7) == 0) lsh[wp * 4 + lh] = lsum;
    if (wp >= 2) {
        #pragma unroll
        for (int h4 = 0; h4 < 4; h4++) {
            u64* dp = (u64*)&scratch[par][h4 * C + lane * 8];
            dp[0] = acc2[h4][0]; dp[1] = acc2[h4][1];
            dp[2] = acc2[h4][2]; dp[3] = acc2[h4][3];
        }
    }
    __syncthreads();
    if (wp < 2) {
        u64 one = pack2(1.f, 1.f);
        #pragma unroll
        for (int h4 = 0; h4 < 4; h4++) {
            u64* dp = (u64*)&scratch[par][h4 * C + lane * 8];
            u64 s0q = dp[0], s1q = dp[1], s2q = dp[2], s3q = dp[3];
            fma2(s0q, one, acc2[h4][0]);
            fma2(s1q, one, acc2[h4][1]);
            fma2(s2q, one, acc2[h4][2]);
            fma2(s3q, one, acc2[h4][3]);
            dp[0] = s0q; dp[1] = s1q; dp[2] = s2q; dp[3] = s3q;
        }
    }
    __syncthreads();
    // scratch flat [2][4*C] == g_agg rows [heads 0-3][heads 4-7] contiguously
    float* gbase = g_agg + d * (H * C);
    const float* sflat = &scratch[0][0];
    for (int idx = t; idx < H * C; idx += 128)
        atomicAdd(&gbase[idx], sflat[idx]);
    if (t < H) atomicAdd(&g_l[d * H + t], lsh[t] + lsh[8 + t]);
}

// ---------------------------------------------------------------------------
// K6: normalize + V projection: out[c] = (agg[c/32]/L) . Wv[c,:] + bv[c]
__global__ void k_vproj(const float* __restrict__ Wv, const float* __restrict__ bv) {
    int d = blockIdx.x;
    int t = threadIdx.x, lane = t & 31, wp = t >> 5;
    __shared__ __align__(16) float agg[H * C];
    __shared__ float Linv[H];
    if (g_bcount[d] == 0) {
        g_outsmall[d * C + t] = 0.f;
        return;
    }
    if (t < H) Linv[t] = 1.f / g_l[d * H + t];
    __syncthreads();
    for (int idx = t; idx < H * C; idx += 256)
        agg[idx] = g_agg[d * (H * C) + idx] * Linv[idx >> 8];
    __syncthreads();
    for (int r = 0; r < 32; r++) {
        int c = wp * 32 + r;
        int h = c >> 5;
        const float4* wr = (const float4*)(Wv + c * C) + lane * 2;
        float4 wa = wr[0], wb = wr[1];
        const float* ar = &agg[h * C + lane * 8];
        float pacc = wa.x * ar[0] + wa.y * ar[1] + wa.z * ar[2] + wa.w * ar[3]
                   + wb.x * ar[4] + wb.y * ar[5] + wb.z * ar[6] + wb.w * ar[7];
        #pragma unroll
        for (int o = 16; o; o >>= 1) pacc += __shfl_xor_sync(0xffffffffu, pacc, o);
        if (lane == 0) g_outsmall[d * C + c] = pacc + bv[c];
    }
}

// ---------------------------------------------------------------------------
// K7: residual + degree + LayerNorm, one warp per row
__global__ void k_ln(const float* __restrict__ x,
                     const float* __restrict__ gamma, const float* __restrict__ beta,
                     float* __restrict__ out, int n) {
    int row = blockIdx.x * 8 + (threadIdx.x >> 5);
    int lane = threadIdx.x & 31;
    if (row >= n) return;
    const float* xr = x + (size_t)row * C + lane * 8;
    float4 a = *(const float4*)(xr);
    float4 b = *(const float4*)(xr + 4);
    float v[8] = {a.x, a.y, a.z, a.w, b.x, b.y, b.z, b.w};
    float degf = (float)g_deg[row];
    #pragma unroll
    for (int j = 0; j < 8; j++) v[j] += degf;
    if (row < NUM_DST) {
        const float* orow = g_outsmall + row * C + lane * 8;
        float4 oa = *(const float4*)(orow);
        float4 ob = *(const float4*)(orow + 4);
        v[0] += oa.x; v[1] += oa.y; v[2] += oa.z; v[3] += oa.w;
        v[4] += ob.x; v[5] += ob.y; v[6] += ob.z; v[7] += ob.w;
    }
    float s = 0.f;
    #pragma unroll
    for (int j = 0; j < 8; j++) s += v[j];
    #pragma unroll
    for (int o = 16; o; o >>= 1) s += __shfl_xor_sync(0xffffffffu, s, o);
    float mu = s * (1.f / C);
    float q = 0.f;
    #pragma unroll
    for (int j = 0; j < 8; j++) { float dd = v[j] - mu; q += dd * dd; }
    #pragma unroll
    for (int o = 16; o; o >>= 1) q += __shfl_xor_sync(0xffffffffu, q, o);
    float rstd = rsqrtf(q * (1.f / C) + LN_EPS);
    const float* gr = gamma + lane * 8;
    const float* br = beta + lane * 8;
    float4 g1 = *(const float4*)(gr);
    float4 g2 = *(const float4*)(gr + 4);
    float4 b1 = *(const float4*)(br);
    float4 b2 = *(const float4*)(br + 4);
    float gv[8] = {g1.x, g1.y, g1.z, g1.w, g2.x, g2.y, g2.z, g2.w};
    float bvv[8] = {b1.x, b1.y, b1.z, b1.w, b2.x, b2.y, b2.z, b2.w};
    float o[8];
    #pragma unroll
    for (int j = 0; j < 8; j++) o[j] = (v[j] - mu) * rstd * gv[j] + bvv[j];
    float* orow = out + (size_t)row * C + lane * 8;
    *(float4*)(orow) = make_float4(o[0], o[1], o[2], o[3]);
    *(float4*)(orow + 4) = make_float4(o[4], o[5], o[6], o[7]);
}

// ---------------------------------------------------------------------------
extern "C" void kernel_launch(void* const* d_in, const int* in_sizes, int n_in,
                              void* d_out, int out_size) {
    const float* x     = (const float*)d_in[0];
    const int*   src   = (const int*)d_in[1];
    const int*   dst   = (const int*)d_in[2];
    const float* Wq    = (const float*)d_in[3];
    const float* bq    = (const float*)d_in[4];
    const float* Wk    = (const float*)d_in[5];
    const float* bk    = (const float*)d_in[6];
    const float* Wv    = (const float*)d_in[7];
    const float* bv    = (const float*)d_in[8];
    const float* spd_w = (const float*)d_in[9];
    const float* gamma = (const float*)d_in[10];
    const float* beta  = (const float*)d_in[11];
    float* out = (float*)d_out;

    int n = in_sizes[0] / C;
    int e = in_sizes[1];
    int initN = (AGGSZ > n) ? AGGSZ : n;

    k_init<<<(initN + 255) / 256, 256>>>(n, bq);
    k_hist<<<HB, 256>>>(src, dst, e);
    k_prebfs<<<1, 256>>>(src, dst);
    k_q<<<dim3(4, 4, 4), 256>>>(x, Wq);            // 4th launch -> ncu capture
    k_u<<<dim3(4, 4, 8), 256>>>(Wk, bk);
    k_scatter<<<HB, 256>>>(src, dst, e);
    k_attn<<<NUM_DST * SPLIT, 128>>>(x, spd_w);
    k_vproj<<<NUM_DST, 256>>>(Wv, bv);
    k_ln<<<(n + 7) / 8, 256>>>(x, gamma, beta, out, n);
}